// round 4
// baseline (speedup 1.0000x reference)
#include <cuda_runtime.h>
#include <cstdint>

#define IMG_H 1024
#define IMG_W 1024
#define TS 32

// direction index -> (dy, dx); idx_neg = idx+4 is the negated offset
__constant__ int c_dy[8] = {0, 1, 1, 1, 0, -1, -1, -1};
__constant__ int c_dx[8] = {1, 1, 0, -1, -1, -1, 0, 1};

// 5-tap gaussian chain in cudnn-style tap order:
// acc = rn(G0*w0); acc = fma(G1,w1,acc); acc = rn(acc+w2) (weight 1.0);
// acc = fma(G1,w3,acc); acc = fma(G0,w4,acc)
__device__ __forceinline__ float blur5(float w0, float w1, float w2, float w3, float w4) {
    const float G0 = 0.13533528323661270f;   // exp(-2)  as fp32
    const float G1 = 0.60653065971263342f;   // exp(-0.5) as fp32
    float a = __fmul_rn(G0, w0);
    a = __fmaf_rn(G1, w1, a);
    a = __fadd_rn(a, w2);
    a = __fmaf_rn(G1, w3, a);
    a = __fmaf_rn(G0, w4, a);
    return a;
}

__global__ __launch_bounds__(256, 4)
void canny_fused(const float* __restrict__ img, float* __restrict__ out) {
    // tile + halo4 input, stride 44 (16B aligned rows for float4)
    __shared__ __align__(16) float sIn[40 * 44];
    __shared__ float sH[40 * 37];     // hblur: rows halo4, cols halo2
    __shared__ float sV[36 * 37];     // blurred: halo2
    __shared__ float sMag[34 * 35];   // grad mag: halo1 (for NMS)
    __shared__ float sGx[34 * 35];
    __shared__ float sGy[34 * 35];

    const int t   = threadIdx.x;
    const int gx0 = blockIdx.x * TS;
    const int gy0 = blockIdx.y * TS;
    const int b   = blockIdx.z;

    #pragma unroll 1
    for (int c = 0; c < 3; c++) {
        const float* src = img + ((size_t)(b * 3 + c)) * (IMG_H * IMG_W);

        // ---- stage 1: load input tile with halo 4, zero-pad outside ----
        for (int i = t; i < 40 * 40; i += 256) {
            int iy = i / 40, ix = i - iy * 40;
            int gr = gy0 - 4 + iy, gc = gx0 - 4 + ix;
            float v = 0.0f;
            if ((unsigned)gr < (unsigned)IMG_H && (unsigned)gc < (unsigned)IMG_W)
                v = __ldg(&src[(size_t)gr * IMG_W + gc]);
            sIn[iy * 44 + ix] = v;
        }
        __syncthreads();

        // ---- stage 2: horizontal 5-tap gaussian (float4 vectorized) ----
        for (int i = t; i < 9 * 40; i += 256) {
            int iy = i / 9, g = i - iy * 9;
            float4 aa = *(const float4*)&sIn[iy * 44 + 4 * g];
            float4 bb = *(const float4*)&sIn[iy * 44 + 4 * g + 4];
            float* dst = &sH[iy * 37 + 4 * g];
            dst[0] = blur5(aa.x, aa.y, aa.z, aa.w, bb.x);
            dst[1] = blur5(aa.y, aa.z, aa.w, bb.x, bb.y);
            dst[2] = blur5(aa.z, aa.w, bb.x, bb.y, bb.z);
            dst[3] = blur5(aa.w, bb.x, bb.y, bb.z, bb.w);
        }
        __syncthreads();

        // ---- stage 3: vertical 5-tap gaussian, sliding window ----
        // Mask result to zero outside the image (reference zero-pads the
        // blurred intermediate before Sobel).
        if (t < 216) {
            int col = t % 36, rg = t / 36;
            int jy0 = rg * 6;
            float w0 = sH[(jy0 + 0) * 37 + col];
            float w1 = sH[(jy0 + 1) * 37 + col];
            float w2 = sH[(jy0 + 2) * 37 + col];
            float w3 = sH[(jy0 + 3) * 37 + col];
            bool colok = (unsigned)(gx0 - 2 + col) < (unsigned)IMG_W;
            #pragma unroll
            for (int j = 0; j < 6; j++) {
                float w4 = sH[(jy0 + 4 + j) * 37 + col];
                float v = blur5(w0, w1, w2, w3, w4);
                if (!colok || (unsigned)(gy0 - 2 + jy0 + j) >= (unsigned)IMG_H)
                    v = 0.0f;
                sV[(jy0 + j) * 37 + col] = v;
                w0 = w1; w1 = w2; w2 = w3; w3 = w4;
            }
        }
        __syncthreads();

        // ---- stage 4: sobel + gradient magnitude ----
        // Row-major tap-order FMA chains (implicit-GEMM accumulation model);
        // per-op rn for the magnitude (matches XLA per-HLO rounding).
        if (t < 204) {
            int col = t % 34, rg = t / 34;
            int my0 = rg * 6;
            int nrows = (rg == 5) ? 4 : 6;
            const float* vp = &sV[my0 * 37 + col];
            float L0 = vp[0],  C0 = vp[1],  R0 = vp[2];
            float L1 = vp[37], C1 = vp[38], R1 = vp[39];
            #pragma unroll
            for (int j = 0; j < 6; j++) {
                if (j >= nrows) break;
                const float* q = &sV[(my0 + 2 + j) * 37 + col];
                float L2 = q[0], C2 = q[1], R2 = q[2];
                // gx: weights [[1,0,-1],[2,0,-2],[1,0,-1]], taps row-major
                float gxv = L0;
                gxv = __fmaf_rn(-1.0f, R0, gxv);
                gxv = __fmaf_rn( 2.0f, L1, gxv);
                gxv = __fmaf_rn(-2.0f, R1, gxv);
                gxv = __fadd_rn(gxv, L2);
                gxv = __fmaf_rn(-1.0f, R2, gxv);
                // gy: weights [[1,2,1],[0,0,0],[-1,-2,-1]], taps row-major
                float gyv = L0;
                gyv = __fmaf_rn( 2.0f, C0, gyv);
                gyv = __fadd_rn(gyv, R0);
                gyv = __fmaf_rn(-1.0f, L2, gyv);
                gyv = __fmaf_rn(-2.0f, C2, gyv);
                gyv = __fmaf_rn(-1.0f, R2, gyv);
                // mag = sqrt((gx*gx + gy*gy) + 1e-8), each op rounded
                float s = __fadd_rn(__fmul_rn(gxv, gxv), __fmul_rn(gyv, gyv));
                s = __fadd_rn(s, 1e-8f);
                float m = __fsqrt_rn(s);
                int my = my0 + j;
                if ((unsigned)(gy0 - 1 + my) >= (unsigned)IMG_H ||
                    (unsigned)(gx0 - 1 + col) >= (unsigned)IMG_W)
                    m = 0.0f;
                int o = my * 35 + col;
                if (c == 0) { sMag[o] = m;  sGx[o] = gxv;  sGy[o] = gyv; }
                else {
                    sMag[o] = __fadd_rn(sMag[o], m);
                    sGx[o]  = __fadd_rn(sGx[o], gxv);
                    sGy[o]  = __fadd_rn(sGy[o], gyv);
                }
                L0 = L1; C0 = C1; R0 = R1;
                L1 = L2; C1 = C2; R1 = R2;
            }
        }
        __syncthreads();
    }

    // ---- stage 5: orientation quantization + NMS + threshold + border ----
    for (int i = t; i < TS * TS; i += 256) {
        int oy = i >> 5, ox = i & 31;
        int gy = gy0 + oy, gx = gx0 + ox;
        int o = (oy + 1) * 35 + (ox + 1);
        float m = sMag[o];
        float ang = atan2f(sGy[o], sGx[o]);
        // match reference fp32 sequence: mul, add, div, round-half-even
        float orient = __fadd_rn(__fmul_rn(ang, 57.295779513082323f), 180.0f);
        float o45 = __fdiv_rn(orient, 45.0f);
        int r = (int)rintf(o45);            // 0..8
        int ip = r & 7;
        int dy = c_dy[ip], dx = c_dx[ip];
        float pos = __fadd_rn(m, -sMag[(oy + 1 + dy) * 35 + (ox + 1 + dx)]);
        float neg = __fadd_rn(m, -sMag[(oy + 1 - dy) * 35 + (ox + 1 - dx)]);
        float res = (fminf(pos, neg) > 0.0f && m >= 1.0f) ? m : 0.0f;
        if (gy == 0 || gy == IMG_H - 1 || gx == 0 || gx == IMG_W - 1)
            res = 0.0f;
        out[((size_t)b << 20) + (size_t)gy * IMG_W + gx] = res;
    }
}

extern "C" void kernel_launch(void* const* d_in, const int* in_sizes, int n_in,
                              void* d_out, int out_size) {
    const float* img = (const float*)d_in[0];
    float* o = (float*)d_out;
    dim3 grid(IMG_W / TS, IMG_H / TS, 8);
    canny_fused<<<grid, 256>>>(img, o);
}

// round 5
// speedup vs baseline: 1.3358x; 1.3358x over previous
#include <cuda_runtime.h>
#include <cstdint>

#define IMG_H 1024
#define IMG_W 1024
#define CHUNK 128            // output rows per warp
#define USEFUL 24            // output cols per warp (lanes 4..27)
#define NSTRIPS 43           // ceil(1024 / 24)
#define WPB 4                // warps per block

__constant__ int c_dy[8] = {0, 1, 1, 1, 0, -1, -1, -1};
__constant__ int c_dx[8] = {1, 1, 0, -1, -1, -1, 0, 1};

// identical chain to the passing R4 kernel — do not touch
__device__ __forceinline__ float blur5(float w0, float w1, float w2, float w3, float w4) {
    const float G0 = 0.13533528323661270f;   // exp(-2)
    const float G1 = 0.60653065971263342f;   // exp(-0.5)
    float a = __fmul_rn(G0, w0);
    a = __fmaf_rn(G1, w1, a);
    a = __fadd_rn(a, w2);
    a = __fmaf_rn(G1, w3, a);
    a = __fmaf_rn(G0, w4, a);
    return a;
}

// select mag neighbor at (row dy, col dx) from the 3x3 register window
__device__ __forceinline__ float pick9(int dy, int dx,
                                       float tl, float tc, float tr,
                                       float cl, float cc, float cr,
                                       float bl, float bc, float br) {
    float rl, rc, rr;
    if (dy < 0)      { rl = tl; rc = tc; rr = tr; }
    else if (dy > 0) { rl = bl; rc = bc; rr = br; }
    else             { rl = cl; rc = cc; rr = cr; }
    return (dx < 0) ? rl : ((dx > 0) ? rr : rc);
}

__global__ __launch_bounds__(128, 5)
void canny_sliding(const float* __restrict__ img, float* __restrict__ out) {
    const unsigned FULL = 0xffffffffu;
    const int lane  = threadIdx.x & 31;
    const int warp  = threadIdx.x >> 5;
    const int strip = blockIdx.x * WPB + warp;
    if (strip >= NSTRIPS) return;

    const int b   = blockIdx.z;
    const int r0  = blockIdx.y * CHUNK;
    const int col = strip * USEFUL + lane - 4;            // may be <0 or >=W in halo lanes
    const bool colok = (unsigned)col < (unsigned)IMG_W;

    const float* p0 = img + ((size_t)(b * 3 + 0) << 20) + col;
    const float* p1 = img + ((size_t)(b * 3 + 1) << 20) + col;
    const float* p2 = img + ((size_t)(b * 3 + 2) << 20) + col;
    float* po = out + ((size_t)b << 20);

    // register pipeline state (all zero-init; garbage rows never consumed)
    float hb[3][4];              // hblur rows ri-4..ri-1
    float vl[3][2], vc[3][2], vr[3][2];  // blurred (L/C/R) rows ri-4, ri-3
    #pragma unroll
    for (int c = 0; c < 3; c++) {
        hb[c][0] = hb[c][1] = hb[c][2] = hb[c][3] = 0.0f;
        vl[c][0] = vl[c][1] = 0.0f;
        vc[c][0] = vc[c][1] = 0.0f;
        vr[c][0] = vr[c][1] = 0.0f;
    }
    float mg_m2 = 0.0f, mg_m1 = 0.0f;    // mag rows ri-5, ri-4
    float ml_m2 = 0.0f, ml_m1 = 0.0f;
    float mr_m2 = 0.0f, mr_m1 = 0.0f;
    float gxs_d = 0.0f, gys_d = 0.0f;    // gx/gy sums at row ri-4

    // preload input row r0-4
    float xc0, xc1, xc2;
    {
        int ri = r0 - 4;
        bool rowok = (unsigned)ri < (unsigned)IMG_H;
        size_t off = (size_t)ri * IMG_W;
        xc0 = (rowok && colok) ? __ldg(p0 + off) : 0.0f;
        xc1 = (rowok && colok) ? __ldg(p1 + off) : 0.0f;
        xc2 = (rowok && colok) ? __ldg(p2 + off) : 0.0f;
    }

    #pragma unroll 2
    for (int ri = r0 - 4; ri <= r0 + CHUNK + 3; ri++) {
        // prefetch next input row (off critical path)
        float xn0 = 0.0f, xn1 = 0.0f, xn2 = 0.0f;
        {
            int rn2 = ri + 1;
            bool rowok = (unsigned)rn2 < (unsigned)IMG_H;
            if (rowok && colok) {
                size_t off = (size_t)rn2 * IMG_W;
                xn0 = __ldg(p0 + off);
                xn1 = __ldg(p1 + off);
                xn2 = __ldg(p2 + off);
            }
        }

        const bool vrowok = (unsigned)(ri - 2) < (unsigned)IMG_H;  // blurred row
        const bool srowok = (unsigned)(ri - 3) < (unsigned)IMG_H;  // sobel/mag row

        float mag_new = 0.0f, gxs = 0.0f, gys = 0.0f;
        float xin[3] = {xc0, xc1, xc2};
        #pragma unroll
        for (int c = 0; c < 3; c++) {
            float x = xin[c];
            // horizontal 5-tap via shuffles (halo lanes produce unused garbage)
            float xm2 = __shfl_up_sync  (FULL, x, 2);
            float xm1 = __shfl_up_sync  (FULL, x, 1);
            float xp1 = __shfl_down_sync(FULL, x, 1);
            float xp2 = __shfl_down_sync(FULL, x, 2);
            float hbn = blur5(xm2, xm1, x, xp1, xp2);

            // vertical 5-tap for blurred row ri-2; mask to zero outside image
            float vbn = blur5(hb[c][0], hb[c][1], hb[c][2], hb[c][3], hbn);
            if (!colok || !vrowok) vbn = 0.0f;
            hb[c][0] = hb[c][1]; hb[c][1] = hb[c][2];
            hb[c][2] = hb[c][3]; hb[c][3] = hbn;

            float vln = __shfl_up_sync  (FULL, vbn, 1);
            float vrn = __shfl_down_sync(FULL, vbn, 1);

            // sobel at row ri-3: rows (ri-4, ri-3, ri-2) = (idx0, idx1, new)
            float L0 = vl[c][0], C0 = vc[c][0], R0 = vr[c][0];
            float L1 = vl[c][1],                R1 = vr[c][1];
            float L2 = vln,      C2 = vbn,      R2 = vrn;
            float gxv = L0;
            gxv = __fmaf_rn(-1.0f, R0, gxv);
            gxv = __fmaf_rn( 2.0f, L1, gxv);
            gxv = __fmaf_rn(-2.0f, R1, gxv);
            gxv = __fadd_rn(gxv, L2);
            gxv = __fmaf_rn(-1.0f, R2, gxv);
            float gyv = L0;
            gyv = __fmaf_rn( 2.0f, C0, gyv);
            gyv = __fadd_rn(gyv, R0);
            gyv = __fmaf_rn(-1.0f, L2, gyv);
            gyv = __fmaf_rn(-2.0f, C2, gyv);
            gyv = __fmaf_rn(-1.0f, R2, gyv);
            float s = __fadd_rn(__fmul_rn(gxv, gxv), __fmul_rn(gyv, gyv));
            s = __fadd_rn(s, 1e-8f);
            float m = __fsqrt_rn(s);
            if (!srowok || !colok) m = 0.0f;

            // channel accumulation, same order/rounding as before
            if (c == 0) { mag_new = m; gxs = gxv; gys = gyv; }
            else {
                mag_new = __fadd_rn(mag_new, m);
                gxs = __fadd_rn(gxs, gxv);
                gys = __fadd_rn(gys, gyv);
            }

            vl[c][0] = vl[c][1]; vl[c][1] = vln;
            vc[c][0] = vc[c][1]; vc[c][1] = vbn;
            vr[c][0] = vr[c][1]; vr[c][1] = vrn;
        }

        float mln = __shfl_up_sync  (FULL, mag_new, 1);
        float mrn = __shfl_down_sync(FULL, mag_new, 1);

        // output row ro = ri-4: mag rows (ro-1, ro, ro+1) = (_m2, _m1, new)
        int ro = ri - 4;
        if (ro >= r0 && lane >= 4 && lane <= 27 && colok) {
            float m = mg_m1;
            float ang = atan2f(gys_d, gxs_d);
            float orient = __fadd_rn(__fmul_rn(ang, 57.295779513082323f), 180.0f);
            float o45 = __fdiv_rn(orient, 45.0f);
            int r = (int)rintf(o45);
            int ip = r & 7;
            int dy = c_dy[ip], dx = c_dx[ip];
            float posn = pick9( dy,  dx, ml_m2, mg_m2, mr_m2,
                                         ml_m1, mg_m1, mr_m1,
                                         mln,   mag_new, mrn);
            float negn = pick9(-dy, -dx, ml_m2, mg_m2, mr_m2,
                                         ml_m1, mg_m1, mr_m1,
                                         mln,   mag_new, mrn);
            float pos = __fadd_rn(m, -posn);
            float neg = __fadd_rn(m, -negn);
            float res = (fminf(pos, neg) > 0.0f && m >= 1.0f) ? m : 0.0f;
            if (ro == 0 || ro == IMG_H - 1 || col == 0 || col == IMG_W - 1)
                res = 0.0f;
            po[(size_t)ro * IMG_W + col] = res;
        }

        // slide windows
        mg_m2 = mg_m1; mg_m1 = mag_new;
        ml_m2 = ml_m1; ml_m1 = mln;
        mr_m2 = mr_m1; mr_m1 = mrn;
        gxs_d = gxs;   gys_d = gys;
        xc0 = xn0; xc1 = xn1; xc2 = xn2;
    }
}

extern "C" void kernel_launch(void* const* d_in, const int* in_sizes, int n_in,
                              void* d_out, int out_size) {
    const float* img = (const float*)d_in[0];
    float* o = (float*)d_out;
    dim3 grid((NSTRIPS + WPB - 1) / WPB, IMG_H / CHUNK, 8);
    canny_sliding<<<grid, WPB * 32>>>(img, o);
}